// round 1
// baseline (speedup 1.0000x reference)
#include <cuda_runtime.h>
#include <math_constants.h>

#define BB 64
#define JJ 32
#define MM 160
#define NN 160
#define HW (MM * NN)   // 25600
#define THREADS 256

__device__ float g_perobj[BB * JJ];

// Kernel A: per-(b,j) argmax over 25600 floats + loss computation.
__global__ __launch_bounds__(THREADS) void argmax_loss_kernel(
    const float* __restrict__ pred,
    const float* __restrict__ gt,
    const float* __restrict__ heatmap)
{
    const int bj = blockIdx.x;                 // 0 .. B*J-1
    const int tid = threadIdx.x;
    const float4* row = reinterpret_cast<const float4*>(heatmap + (size_t)bj * HW);

    float best = -CUDART_INF_F;
    int bidx = 0;

    // 6400 float4 per row; 256 threads -> 25 iterations each.
    #pragma unroll 5
    for (int i = tid; i < HW / 4; i += THREADS) {
        float4 v = row[i];
        int base = i * 4;
        // strictly-greater keeps the earliest index within a thread
        if (v.x > best) { best = v.x; bidx = base; }
        if (v.y > best) { best = v.y; bidx = base + 1; }
        if (v.z > best) { best = v.z; bidx = base + 2; }
        if (v.w > best) { best = v.w; bidx = base + 3; }
    }

    __shared__ float svals[THREADS];
    __shared__ int   sidx[THREADS];
    svals[tid] = best;
    sidx[tid]  = bidx;
    __syncthreads();

    // tree reduction with first-index tie-break
    for (int s = THREADS / 2; s > 0; s >>= 1) {
        if (tid < s) {
            float ov = svals[tid + s];
            int   oi = sidx[tid + s];
            if (ov > svals[tid] || (ov == svals[tid] && oi < sidx[tid])) {
                svals[tid] = ov;
                sidx[tid]  = oi;
            }
        }
        __syncthreads();
    }

    if (tid == 0) {
        int idx = sidx[0];
        float x = (float)(idx / MM);   // reference: idx // m
        float y = (float)(idx % MM);   // reference: idx %  m

        int b = bj / JJ;
        int j = bj % JJ;

        const float* g = gt + ((size_t)b * JJ + j) * 11;
        float g7 = g[7], g8 = g[8], g9 = g[9], g10 = g[10];
        bool valid = (g9 > 0.0f) && (g10 > 0.0f) && (g9 < (float)MM) && (g10 < (float)NN);

        // pred layout: (B, 9, J, 1) -> pred[((b*9 + c)*J) + j]
        const float* pb = pred + (size_t)b * 9 * JJ + j;
        float px = pb[7 * JJ];
        float py = pb[8 * JJ];

        float dx = g9 + g7 - x - px;
        float dy = g10 + g8 - y - py;
        float loss = dx * dx + dy * dy;

        float cls = 0.0f;
        #pragma unroll
        for (int c = 0; c < 7; c++) {
            float d = pb[c * JJ] - g[c];
            cls = fmaf(d, d, cls);
        }

        g_perobj[bj] = valid ? (cls + loss) : 0.0f;
    }
}

// Kernel B: sum 32 per-joint losses per batch -> d_out[b]. One warp per batch.
__global__ void reduce_kernel(float* __restrict__ out)
{
    int b = blockIdx.x;           // 0..63
    int lane = threadIdx.x;       // 0..31
    float v = g_perobj[b * JJ + lane];
    #pragma unroll
    for (int off = 16; off > 0; off >>= 1)
        v += __shfl_down_sync(0xFFFFFFFFu, v, off);
    if (lane == 0) out[b] = v;
}

extern "C" void kernel_launch(void* const* d_in, const int* in_sizes, int n_in,
                              void* d_out, int out_size)
{
    const float* pred    = (const float*)d_in[0];
    const float* gt      = (const float*)d_in[1];
    const float* heatmap = (const float*)d_in[2];
    float* out = (float*)d_out;

    argmax_loss_kernel<<<BB * JJ, THREADS>>>(pred, gt, heatmap);
    reduce_kernel<<<BB, 32>>>(out);
}